// round 1
// baseline (speedup 1.0000x reference)
#include <cuda_runtime.h>
#include <cuda_bf16.h>

// Problem constants
constexpr int BB    = 8;      // batch
constexpr int HH    = 32;     // height
constexpr int WWI   = 32;     // width
constexpr int NN    = 1024;   // tokens = H*W
constexpr int CD    = 512;    // dim
constexpr int NHEAD = 16;
constexpr int HD    = 32;     // head dim
constexpr int MTOT  = BB * NN;   // 8192 rows

// Scratch (device globals; no allocation allowed)
__device__ float g_qkv[3 * BB * NHEAD * NN * HD];  // [3][B][h][N][d]
__device__ float g_y[MTOT * CD];                   // attn out + lepe, [B*N, C]

// ---------------------------------------------------------------------------
// Tiled SGEMM: out = A[M x K] @ W^T, W is [N x K] row-major.
// MODE 0: scatter into g_qkv per (three, head, d) decomposition of column.
// MODE 1: out[r*N + c] = acc + bias[c]   (writes to `out`)
// ---------------------------------------------------------------------------
template <int MODE>
__global__ __launch_bounds__(256) void gemm_kernel(
    const float* __restrict__ A, const float* __restrict__ W,
    const float* __restrict__ bias, float* __restrict__ out,
    int M, int N, int K)
{
    constexpr int BM = 128, BN = 128, BK = 8, TM = 8, TN = 8;
    __shared__ float As[BK * BM];
    __shared__ float Bs[BK * BN];

    const int tid = threadIdx.x;
    const int tx = tid % 16;       // 0..15 -> N direction
    const int ty = tid / 16;       // 0..15 -> M direction
    const int rowBase = blockIdx.y * BM;
    const int colBase = blockIdx.x * BN;

    const int lrow = tid >> 1;        // 0..127
    const int lcol = (tid & 1) * 4;   // 0 or 4

    float acc[TM][TN];
    #pragma unroll
    for (int i = 0; i < TM; i++)
        #pragma unroll
        for (int j = 0; j < TN; j++) acc[i][j] = 0.0f;

    const float* aPtr = A + (size_t)(rowBase + lrow) * K + lcol;
    const float* wPtr = W + (size_t)(colBase + lrow) * K + lcol;

    for (int kt = 0; kt < K; kt += BK) {
        float4 av = *(const float4*)(aPtr + kt);
        float4 wv = *(const float4*)(wPtr + kt);
        As[(lcol + 0) * BM + lrow] = av.x;
        As[(lcol + 1) * BM + lrow] = av.y;
        As[(lcol + 2) * BM + lrow] = av.z;
        As[(lcol + 3) * BM + lrow] = av.w;
        Bs[(lcol + 0) * BN + lrow] = wv.x;
        Bs[(lcol + 1) * BN + lrow] = wv.y;
        Bs[(lcol + 2) * BN + lrow] = wv.z;
        Bs[(lcol + 3) * BN + lrow] = wv.w;
        __syncthreads();

        #pragma unroll
        for (int k = 0; k < BK; k++) {
            float ra[TM], rb[TN];
            #pragma unroll
            for (int i = 0; i < TM; i += 4) {
                float4 t = *(const float4*)&As[k * BM + ty * TM + i];
                ra[i] = t.x; ra[i+1] = t.y; ra[i+2] = t.z; ra[i+3] = t.w;
            }
            #pragma unroll
            for (int j = 0; j < TN; j += 4) {
                float4 t = *(const float4*)&Bs[k * BN + tx * TN + j];
                rb[j] = t.x; rb[j+1] = t.y; rb[j+2] = t.z; rb[j+3] = t.w;
            }
            #pragma unroll
            for (int i = 0; i < TM; i++)
                #pragma unroll
                for (int j = 0; j < TN; j++)
                    acc[i][j] = fmaf(ra[i], rb[j], acc[i][j]);
        }
        __syncthreads();
    }

    #pragma unroll
    for (int i = 0; i < TM; i++) {
        const int r = rowBase + ty * TM + i;
        #pragma unroll
        for (int j = 0; j < TN; j++) {
            const int c = colBase + tx * TN + j;
            float v = acc[i][j];
            if (MODE == 0) {
                // qkv column decomposition: c = three*512 + head*32 + d
                const int three = c >> 9;
                const int head  = (c >> 5) & 15;
                const int d     = c & 31;
                const int b     = r >> 10;
                const int n     = r & 1023;
                g_qkv[((((size_t)three * BB + b) * NHEAD + head) * NN + n) * HD + d] = v;
            } else {
                out[(size_t)r * N + c] = v + bias[c];
            }
        }
    }
}

// ---------------------------------------------------------------------------
// Flash-style attention: 1 thread = 1 query row. K/V tiles of 64 keys in smem.
// grid = (N/128, NHEAD, B), block = 128.
// ---------------------------------------------------------------------------
__global__ __launch_bounds__(128) void attn_kernel(float* __restrict__ y)
{
    __shared__ float Ks[64 * HD];
    __shared__ float Vs[64 * HD];

    const int b = blockIdx.z;
    const int h = blockIdx.y;
    const int n = blockIdx.x * 128 + threadIdx.x;
    const float scale = 0.17677669529663687f;  // 32^-0.5

    const float* qp = g_qkv + ((((size_t)0 * BB + b) * NHEAD + h) * NN + n) * HD;
    const float* kb = g_qkv + ((((size_t)1 * BB + b) * NHEAD + h) * NN) * HD;
    const float* vb = g_qkv + ((((size_t)2 * BB + b) * NHEAD + h) * NN) * HD;

    float q[HD];
    #pragma unroll
    for (int d = 0; d < HD; d += 4) {
        float4 t = *(const float4*)&qp[d];
        q[d] = t.x; q[d+1] = t.y; q[d+2] = t.z; q[d+3] = t.w;
    }

    float acc[HD];
    #pragma unroll
    for (int d = 0; d < HD; d++) acc[d] = 0.0f;
    float m = -1e30f, l = 0.0f;

    for (int kt = 0; kt < NN; kt += 64) {
        __syncthreads();
        // cooperative load: 64*32 floats = 512 float4
        const float4* ksrc = (const float4*)(kb + (size_t)kt * HD);
        const float4* vsrc = (const float4*)(vb + (size_t)kt * HD);
        for (int i = threadIdx.x; i < 512; i += 128) {
            ((float4*)Ks)[i] = ksrc[i];
            ((float4*)Vs)[i] = vsrc[i];
        }
        __syncthreads();

        for (int j = 0; j < 64; j++) {
            float s = 0.0f;
            #pragma unroll
            for (int d = 0; d < HD; d++) s = fmaf(q[d], Ks[j * HD + d], s);
            s *= scale;
            if (s > m) {
                const float cf = __expf(m - s);   // 0 on first hit (m=-1e30)
                l *= cf;
                #pragma unroll
                for (int d = 0; d < HD; d++) acc[d] *= cf;
                m = s;
            }
            const float p = __expf(s - m);
            l += p;
            #pragma unroll
            for (int d = 0; d < HD; d++) acc[d] = fmaf(p, Vs[j * HD + d], acc[d]);
        }
    }

    const float inv = 1.0f / l;
    float* yp = y + ((size_t)(b * NN + n)) * CD + h * HD;
    #pragma unroll
    for (int d = 0; d < HD; d += 4) {
        float4 t;
        t.x = acc[d] * inv; t.y = acc[d+1] * inv;
        t.z = acc[d+2] * inv; t.w = acc[d+3] * inv;
        *(float4*)&yp[d] = t;
    }
}

// ---------------------------------------------------------------------------
// LePE depthwise 5x5 conv, channels-last; y += conv(x) + bias
// grid = (W, H, B), block = 128 threads (4 channels each via float4)
// ---------------------------------------------------------------------------
__global__ __launch_bounds__(128) void lepe_kernel(
    const float* __restrict__ x, const float* __restrict__ wl,
    const float* __restrict__ bl, float* __restrict__ y)
{
    const int b  = blockIdx.z;
    const int yy = blockIdx.y;
    const int xx = blockIdx.x;
    const int c  = threadIdx.x * 4;

    float4 sum = *(const float4*)&bl[c];
    #pragma unroll
    for (int ky = 0; ky < 5; ky++) {
        const int iy = yy + ky - 2;
        if (iy < 0 || iy >= HH) continue;
        #pragma unroll
        for (int kx = 0; kx < 5; kx++) {
            const int ix = xx + kx - 2;
            if (ix < 0 || ix >= WWI) continue;
            const float4 xv = *(const float4*)&x[(((size_t)(b * HH + iy) * WWI + ix) * CD) + c];
            const int wk = ky * 5 + kx;
            sum.x = fmaf(xv.x, wl[(c + 0) * 25 + wk], sum.x);
            sum.y = fmaf(xv.y, wl[(c + 1) * 25 + wk], sum.y);
            sum.z = fmaf(xv.z, wl[(c + 2) * 25 + wk], sum.z);
            sum.w = fmaf(xv.w, wl[(c + 3) * 25 + wk], sum.w);
        }
    }
    float* yp = &y[(((size_t)b * NN + yy * WWI + xx) * CD) + c];
    float4 cur = *(float4*)yp;
    cur.x += sum.x; cur.y += sum.y; cur.z += sum.z; cur.w += sum.w;
    *(float4*)yp = cur;
}

// ---------------------------------------------------------------------------
extern "C" void kernel_launch(void* const* d_in, const int* in_sizes, int n_in,
                              void* d_out, int out_size)
{
    const float* x      = (const float*)d_in[0];  // [8,32,32,512]
    const float* w_qkv  = (const float*)d_in[1];  // [1536,512]
    const float* w_proj = (const float*)d_in[2];  // [512,512]
    const float* b_proj = (const float*)d_in[3];  // [512]
    const float* w_lepe = (const float*)d_in[4];  // [512,1,5,5]
    const float* b_lepe = (const float*)d_in[5];  // [512]
    float* out = (float*)d_out;

    float* yPtr;
    cudaGetSymbolAddress((void**)&yPtr, g_y);

    // 1) QKV projection -> g_qkv  (M=8192, N=1536, K=512)
    {
        dim3 grid(3 * CD / 128, MTOT / 128);
        gemm_kernel<0><<<grid, 256>>>(x, w_qkv, nullptr, nullptr, MTOT, 3 * CD, CD);
    }
    // 2) Attention -> g_y
    {
        dim3 grid(NN / 128, NHEAD, BB);
        attn_kernel<<<grid, 128>>>(yPtr);
    }
    // 3) LePE: g_y += dwconv(x)
    {
        dim3 grid(WWI, HH, BB);
        lepe_kernel<<<grid, 128>>>(x, w_lepe, b_lepe, yPtr);
    }
    // 4) Output projection -> d_out  (M=8192, N=512, K=512)
    {
        dim3 grid(CD / 128, MTOT / 128);
        gemm_kernel<1><<<grid, 256>>>(yPtr, w_proj, b_proj, out, MTOT, CD, CD);
    }
}

// round 3
// speedup vs baseline: 1.3733x; 1.3733x over previous
#include <cuda_runtime.h>
#include <cuda_bf16.h>
#include <cstdint>

// Problem constants
constexpr int BB    = 8;      // batch
constexpr int HH    = 32;     // height
constexpr int WWI   = 32;     // width
constexpr int NN    = 1024;   // tokens = H*W
constexpr int CD    = 512;    // dim
constexpr int NHEAD = 16;
constexpr int HD    = 32;     // head dim
constexpr int MTOT  = BB * NN;   // 8192 rows
constexpr int KKG   = 512;       // GEMM K (both GEMMs)

// ---------------------------------------------------------------------------
// Scratch (device globals; no allocation allowed)
// ---------------------------------------------------------------------------
__device__ float g_qkv[3 * BB * NHEAD * NN * HD];   // [3][B][h][N][d]
__device__ float g_y[MTOT * CD];                    // attn out + lepe
__device__ __nv_bfloat16 g_xh[MTOT * CD],  g_xl[MTOT * CD];
__device__ __nv_bfloat16 g_yh[MTOT * CD],  g_yl[MTOT * CD];
__device__ __nv_bfloat16 g_wqh[3 * CD * CD], g_wql[3 * CD * CD];
__device__ __nv_bfloat16 g_wph[CD * CD],     g_wpl[CD * CD];

// ---------------------------------------------------------------------------
// PTX helpers — sm_103-base ISA only (NO tcgen05: harness PTX targets sm_103)
// ---------------------------------------------------------------------------
__device__ __forceinline__ uint32_t smem_u32(const void* p) {
    uint32_t a;
    asm("{ .reg .u64 t; cvta.to.shared.u64 t, %1; cvt.u32.u64 %0, t; }" : "=r"(a) : "l"(p));
    return a;
}

__device__ __forceinline__ void cp_async16(uint32_t s, const void* g) {
    asm volatile("cp.async.cg.shared.global [%0], [%1], 16;" :: "r"(s), "l"(g));
}

#define CP_COMMIT() asm volatile("cp.async.commit_group;")

#define LDSM_X4(R, addr)                                                     \
    asm volatile("ldmatrix.sync.aligned.m8n8.x4.shared.b16 {%0,%1,%2,%3}, [%4];" \
        : "=r"((R)[0]), "=r"((R)[1]), "=r"((R)[2]), "=r"((R)[3]) : "r"(addr))

#define MMA16816(C, A, B0, B1)                                               \
    asm volatile("mma.sync.aligned.m16n8k16.row.col.f32.bf16.bf16.f32 "      \
        "{%0,%1,%2,%3}, {%4,%5,%6,%7}, {%8,%9}, {%0,%1,%2,%3};"              \
        : "+f"((C)[0]), "+f"((C)[1]), "+f"((C)[2]), "+f"((C)[3])             \
        : "r"((A)[0]), "r"((A)[1]), "r"((A)[2]), "r"((A)[3]),                \
          "r"(B0), "r"(B1))

// ---------------------------------------------------------------------------
// fp32 -> (bf16 hi, bf16 lo) split; float4 per thread
// ---------------------------------------------------------------------------
__global__ __launch_bounds__(256) void split_kernel(
    const float* __restrict__ s, __nv_bfloat16* __restrict__ hi,
    __nv_bfloat16* __restrict__ lo, int n4)
{
    int i = blockIdx.x * blockDim.x + threadIdx.x;
    if (i >= n4) return;
    float4 v = ((const float4*)s)[i];
    __nv_bfloat16 h0 = __float2bfloat16(v.x);
    __nv_bfloat16 h1 = __float2bfloat16(v.y);
    __nv_bfloat16 h2 = __float2bfloat16(v.z);
    __nv_bfloat16 h3 = __float2bfloat16(v.w);
    __nv_bfloat16 l0 = __float2bfloat16(v.x - __bfloat162float(h0));
    __nv_bfloat16 l1 = __float2bfloat16(v.y - __bfloat162float(h1));
    __nv_bfloat16 l2 = __float2bfloat16(v.z - __bfloat162float(h2));
    __nv_bfloat16 l3 = __float2bfloat16(v.w - __bfloat162float(h3));
    __nv_bfloat162* H = (__nv_bfloat162*)hi;
    __nv_bfloat162* L = (__nv_bfloat162*)lo;
    H[2 * i]     = __nv_bfloat162(h0, h1);
    H[2 * i + 1] = __nv_bfloat162(h2, h3);
    L[2 * i]     = __nv_bfloat162(l0, l1);
    L[2 * i + 1] = __nv_bfloat162(l2, l3);
}

// ---------------------------------------------------------------------------
// bf16x3 GEMM via mma.sync:  D[128x128] = (Ah+Al)[128xK] @ (Bh+Bl)[128xK]^T
// MODE 0: scatter into g_qkv (QKV projection).  MODE 1: out = D + bias.
// 256 threads (8 warps: 4 M x 2 N), warp tile 32x64, K-chunk 32, 2-stage
// cp.async pipeline. Smem tiles stride = 40 bf16 (80B) -> ldmatrix conflict-free.
// ---------------------------------------------------------------------------
template <int MODE>
__global__ __launch_bounds__(256) void mma_gemm(
    const __nv_bfloat16* __restrict__ Ah, const __nv_bfloat16* __restrict__ Al,
    const __nv_bfloat16* __restrict__ Bh, const __nv_bfloat16* __restrict__ Bl,
    const float* __restrict__ bias, float* __restrict__ out)
{
    constexpr int ROWB  = 80;                 // bytes per smem row (40 bf16)
    constexpr int TILE  = 128 * ROWB;         // 10240 B
    constexpr int STAGE = 4 * TILE;           // Ah, Al, Bh, Bl
    constexpr int NCH   = KKG / 32;           // 16 K-chunks

    extern __shared__ char dsm[];
    const uint32_t sbase = smem_u32(dsm);

    const int tid  = threadIdx.x;
    const int lane = tid & 31;
    const int wid  = tid >> 5;
    const int mw   = wid & 3;                 // 0..3 -> M groups of 32
    const int nw   = wid >> 2;                // 0..1 -> N groups of 64
    const int rowBase = blockIdx.y * 128;
    const int colBase = blockIdx.x * 128;

    float acc[2][8][4];
    #pragma unroll
    for (int a = 0; a < 2; a++)
        #pragma unroll
        for (int b = 0; b < 8; b++)
            #pragma unroll
            for (int c = 0; c < 4; c++) acc[a][b][c] = 0.0f;

    // ldmatrix per-lane relative offsets
    const uint32_t aOff = (uint32_t)((mw * 32 + (lane & 15)) * ROWB + (lane >> 4) * 16);
    const int mi   = lane >> 3;
    const uint32_t bOff = (uint32_t)((nw * 64 + (mi >> 1) * 8 + (lane & 7)) * ROWB + (mi & 1) * 16);

    auto loadChunk = [&](int ch, int buf) {
        const uint32_t sb = sbase + buf * STAGE;
        #pragma unroll
        for (int rep = 0; rep < 2; rep++) {
            const int id  = tid * 2 + rep;
            const int r   = id >> 2;
            const int seg = id & 3;
            const uint32_t so = (uint32_t)(r * ROWB + seg * 16);
            const size_t  ga = (size_t)(rowBase + r) * KKG + ch * 32 + seg * 8;
            const size_t  gb = (size_t)(colBase + r) * KKG + ch * 32 + seg * 8;
            cp_async16(sb + so,            Ah + ga);
            cp_async16(sb + TILE + so,     Al + ga);
            cp_async16(sb + 2 * TILE + so, Bh + gb);
            cp_async16(sb + 3 * TILE + so, Bl + gb);
        }
    };

    loadChunk(0, 0);
    CP_COMMIT();

    for (int ch = 0; ch < NCH; ch++) {
        if (ch + 1 < NCH) {
            loadChunk(ch + 1, (ch + 1) & 1);
            CP_COMMIT();
            asm volatile("cp.async.wait_group 1;");
        } else {
            asm volatile("cp.async.wait_group 0;");
        }
        __syncthreads();

        const uint32_t st = sbase + (ch & 1) * STAGE;
        #pragma unroll
        for (int ks = 0; ks < 2; ks++) {
            const uint32_t ko = ks * 32;
            uint32_t ah[2][4], al[2][4], bb[4][4];
            #pragma unroll
            for (int mm = 0; mm < 2; mm++) {
                LDSM_X4(ah[mm], st + aOff + mm * (16 * ROWB) + ko);
                LDSM_X4(al[mm], st + TILE + aOff + mm * (16 * ROWB) + ko);
            }
            #pragma unroll
            for (int nb = 0; nb < 4; nb++)
                LDSM_X4(bb[nb], st + 2 * TILE + bOff + nb * (16 * ROWB) + ko);

            #pragma unroll
            for (int mm = 0; mm < 2; mm++)
                #pragma unroll
                for (int nf = 0; nf < 8; nf++) {
                    const uint32_t b0 = bb[nf >> 1][(nf & 1) * 2];
                    const uint32_t b1 = bb[nf >> 1][(nf & 1) * 2 + 1];
                    MMA16816(acc[mm][nf], ah[mm], b0, b1);
                    MMA16816(acc[mm][nf], al[mm], b0, b1);
                }

            #pragma unroll
            for (int nb = 0; nb < 4; nb++)
                LDSM_X4(bb[nb], st + 3 * TILE + bOff + nb * (16 * ROWB) + ko);

            #pragma unroll
            for (int mm = 0; mm < 2; mm++)
                #pragma unroll
                for (int nf = 0; nf < 8; nf++) {
                    const uint32_t b0 = bb[nf >> 1][(nf & 1) * 2];
                    const uint32_t b1 = bb[nf >> 1][(nf & 1) * 2 + 1];
                    MMA16816(acc[mm][nf], ah[mm], b0, b1);
                }
        }
        __syncthreads();
    }

    // Epilogue. C frag: rows lane/4 (+8), cols (lane%4)*2
    #pragma unroll
    for (int mm = 0; mm < 2; mm++) {
        #pragma unroll
        for (int nf = 0; nf < 8; nf++) {
            const int c = colBase + nw * 64 + nf * 8 + (lane & 3) * 2;
            const int r0 = rowBase + mw * 32 + mm * 16 + (lane >> 2);
            if (MODE == 0) {
                const int three = c >> 9;
                const int head  = (c >> 5) & 15;
                const int d     = c & 31;
                #pragma unroll
                for (int half = 0; half < 2; half++) {
                    const int r = r0 + half * 8;
                    const int b = r >> 10, n = r & 1023;
                    float* dst = g_qkv + ((((size_t)three * BB + b) * NHEAD + head) * NN + n) * HD + d;
                    float2 v = make_float2(acc[mm][nf][half * 2], acc[mm][nf][half * 2 + 1]);
                    *(float2*)dst = v;
                }
            } else {
                const float2 bv = *(const float2*)(bias + c);
                #pragma unroll
                for (int half = 0; half < 2; half++) {
                    const int r = r0 + half * 8;
                    float2 v = make_float2(acc[mm][nf][half * 2] + bv.x,
                                           acc[mm][nf][half * 2 + 1] + bv.y);
                    *(float2*)(out + (size_t)r * CD + c) = v;
                }
            }
        }
    }
}

// ---------------------------------------------------------------------------
// Flash-style attention: 1 thread = 1 query row (fp32)
// ---------------------------------------------------------------------------
__global__ __launch_bounds__(128) void attn_kernel(float* __restrict__ y)
{
    __shared__ float Ks[64 * HD];
    __shared__ float Vs[64 * HD];

    const int b = blockIdx.z;
    const int h = blockIdx.y;
    const int n = blockIdx.x * 128 + threadIdx.x;
    const float scale = 0.17677669529663687f;

    const float* qp = g_qkv + ((((size_t)0 * BB + b) * NHEAD + h) * NN + n) * HD;
    const float* kb = g_qkv + ((((size_t)1 * BB + b) * NHEAD + h) * NN) * HD;
    const float* vb = g_qkv + ((((size_t)2 * BB + b) * NHEAD + h) * NN) * HD;

    float q[HD];
    #pragma unroll
    for (int d = 0; d < HD; d += 4) {
        float4 t = *(const float4*)&qp[d];
        q[d] = t.x; q[d+1] = t.y; q[d+2] = t.z; q[d+3] = t.w;
    }

    float acc[HD];
    #pragma unroll
    for (int d = 0; d < HD; d++) acc[d] = 0.0f;
    float m = -1e30f, l = 0.0f;

    for (int kt = 0; kt < NN; kt += 64) {
        __syncthreads();
        const float4* ksrc = (const float4*)(kb + (size_t)kt * HD);
        const float4* vsrc = (const float4*)(vb + (size_t)kt * HD);
        for (int i = threadIdx.x; i < 512; i += 128) {
            ((float4*)Ks)[i] = ksrc[i];
            ((float4*)Vs)[i] = vsrc[i];
        }
        __syncthreads();

        for (int j = 0; j < 64; j++) {
            float s = 0.0f;
            #pragma unroll
            for (int d = 0; d < HD; d++) s = fmaf(q[d], Ks[j * HD + d], s);
            s *= scale;
            if (s > m) {
                const float cf = __expf(m - s);
                l *= cf;
                #pragma unroll
                for (int d = 0; d < HD; d++) acc[d] *= cf;
                m = s;
            }
            const float p = __expf(s - m);
            l += p;
            #pragma unroll
            for (int d = 0; d < HD; d++) acc[d] = fmaf(p, Vs[j * HD + d], acc[d]);
        }
    }

    const float inv = 1.0f / l;
    float* yp = y + ((size_t)(b * NN + n)) * CD + h * HD;
    #pragma unroll
    for (int d = 0; d < HD; d += 4) {
        float4 t;
        t.x = acc[d] * inv; t.y = acc[d+1] * inv;
        t.z = acc[d+2] * inv; t.w = acc[d+3] * inv;
        *(float4*)&yp[d] = t;
    }
}

// ---------------------------------------------------------------------------
// LePE depthwise 5x5 conv, channels-last; y += conv(x) + bias
// ---------------------------------------------------------------------------
__global__ __launch_bounds__(128) void lepe_kernel(
    const float* __restrict__ x, const float* __restrict__ wl,
    const float* __restrict__ bl, float* __restrict__ y)
{
    const int b  = blockIdx.z;
    const int yy = blockIdx.y;
    const int xx = blockIdx.x;
    const int c  = threadIdx.x * 4;

    float4 sum = *(const float4*)&bl[c];
    #pragma unroll
    for (int ky = 0; ky < 5; ky++) {
        const int iy = yy + ky - 2;
        if (iy < 0 || iy >= HH) continue;
        #pragma unroll
        for (int kx = 0; kx < 5; kx++) {
            const int ix = xx + kx - 2;
            if (ix < 0 || ix >= WWI) continue;
            const float4 xv = *(const float4*)&x[(((size_t)(b * HH + iy) * WWI + ix) * CD) + c];
            const int wk = ky * 5 + kx;
            sum.x = fmaf(xv.x, wl[(c + 0) * 25 + wk], sum.x);
            sum.y = fmaf(xv.y, wl[(c + 1) * 25 + wk], sum.y);
            sum.z = fmaf(xv.z, wl[(c + 2) * 25 + wk], sum.z);
            sum.w = fmaf(xv.w, wl[(c + 3) * 25 + wk], sum.w);
        }
    }
    float* yp = &y[(((size_t)b * NN + yy * WWI + xx) * CD) + c];
    float4 cur = *(float4*)yp;
    cur.x += sum.x; cur.y += sum.y; cur.z += sum.z; cur.w += sum.w;
    *(float4*)yp = cur;
}

// ---------------------------------------------------------------------------
extern "C" void kernel_launch(void* const* d_in, const int* in_sizes, int n_in,
                              void* d_out, int out_size)
{
    const float* x      = (const float*)d_in[0];
    const float* w_qkv  = (const float*)d_in[1];
    const float* w_proj = (const float*)d_in[2];
    const float* b_proj = (const float*)d_in[3];
    const float* w_lepe = (const float*)d_in[4];
    const float* b_lepe = (const float*)d_in[5];
    float* out = (float*)d_out;

    float *yPtr;
    __nv_bfloat16 *xh, *xl, *yh, *yl, *wqh, *wql, *wph, *wpl;
    cudaGetSymbolAddress((void**)&yPtr, g_y);
    cudaGetSymbolAddress((void**)&xh, g_xh);   cudaGetSymbolAddress((void**)&xl, g_xl);
    cudaGetSymbolAddress((void**)&yh, g_yh);   cudaGetSymbolAddress((void**)&yl, g_yl);
    cudaGetSymbolAddress((void**)&wqh, g_wqh); cudaGetSymbolAddress((void**)&wql, g_wql);
    cudaGetSymbolAddress((void**)&wph, g_wph); cudaGetSymbolAddress((void**)&wpl, g_wpl);

    constexpr int SMEM_DYN = 2 * 4 * 128 * 80;   // 81920 B (2-stage x 4 tiles)
    cudaFuncSetAttribute(mma_gemm<0>, cudaFuncAttributeMaxDynamicSharedMemorySize, SMEM_DYN);
    cudaFuncSetAttribute(mma_gemm<1>, cudaFuncAttributeMaxDynamicSharedMemorySize, SMEM_DYN);

    // 0) split inputs/weights to bf16 hi/lo
    {
        int n4 = MTOT * CD / 4;
        split_kernel<<<(n4 + 255) / 256, 256>>>(x, xh, xl, n4);
        int w4 = 3 * CD * CD / 4;
        split_kernel<<<(w4 + 255) / 256, 256>>>(w_qkv, wqh, wql, w4);
        int p4 = CD * CD / 4;
        split_kernel<<<(p4 + 255) / 256, 256>>>(w_proj, wph, wpl, p4);
    }
    // 1) QKV projection -> g_qkv   (M=8192, N=1536, K=512)
    {
        dim3 grid(3 * CD / 128, MTOT / 128);
        mma_gemm<0><<<grid, 256, SMEM_DYN>>>(xh, xl, wqh, wql, nullptr, nullptr);
    }
    // 2) Attention -> g_y
    {
        dim3 grid(NN / 128, NHEAD, BB);
        attn_kernel<<<grid, 128>>>(yPtr);
    }
    // 3) LePE: g_y += dwconv(x)
    {
        dim3 grid(WWI, HH, BB);
        lepe_kernel<<<grid, 128>>>(x, w_lepe, b_lepe, yPtr);
    }
    // 4) split y, then output projection -> d_out  (M=8192, N=512, K=512)
    {
        int n4 = MTOT * CD / 4;
        split_kernel<<<(n4 + 255) / 256, 256>>>(yPtr, yh, yl, n4);
        dim3 grid(CD / 128, MTOT / 128);
        mma_gemm<1><<<grid, 256, SMEM_DYN>>>(yh, yl, wph, wpl, b_proj, out);
    }
}

// round 4
// speedup vs baseline: 1.5589x; 1.1352x over previous
#include <cuda_runtime.h>
#include <cuda_bf16.h>
#include <cstdint>

// Problem constants
constexpr int BB    = 8;      // batch
constexpr int HH    = 32;     // height
constexpr int WWI   = 32;     // width
constexpr int NN    = 1024;   // tokens = H*W
constexpr int CD    = 512;    // dim
constexpr int NHEAD = 16;
constexpr int HD    = 32;     // head dim
constexpr int MTOT  = BB * NN;   // 8192 rows
constexpr int KKG   = 512;       // GEMM K (both GEMMs)

// ---------------------------------------------------------------------------
// Scratch (device globals; no allocation allowed)
// ---------------------------------------------------------------------------
__device__ float g_y[MTOT * CD];                    // attn out + lepe
__device__ __nv_bfloat16 g_xh[MTOT * CD],  g_xl[MTOT * CD];
__device__ __nv_bfloat16 g_yh[MTOT * CD],  g_yl[MTOT * CD];
__device__ __nv_bfloat16 g_wqh[3 * CD * CD], g_wql[3 * CD * CD];
__device__ __nv_bfloat16 g_wph[CD * CD],     g_wpl[CD * CD];
// Q/K/V in bf16 hi/lo, layout [(b*NHEAD+h)][N][HD]
constexpr int QKV_ELEMS = BB * NHEAD * NN * HD;
__device__ __nv_bfloat16 g_qh[QKV_ELEMS], g_ql[QKV_ELEMS];
__device__ __nv_bfloat16 g_kh[QKV_ELEMS], g_kl[QKV_ELEMS];
__device__ __nv_bfloat16 g_vh[QKV_ELEMS], g_vl[QKV_ELEMS];

// ---------------------------------------------------------------------------
// PTX helpers — sm_103-base ISA only (NO tcgen05: harness PTX targets sm_103)
// ---------------------------------------------------------------------------
__device__ __forceinline__ uint32_t smem_u32(const void* p) {
    uint32_t a;
    asm("{ .reg .u64 t; cvta.to.shared.u64 t, %1; cvt.u32.u64 %0, t; }" : "=r"(a) : "l"(p));
    return a;
}

__device__ __forceinline__ void cp_async16(uint32_t s, const void* g) {
    asm volatile("cp.async.cg.shared.global [%0], [%1], 16;" :: "r"(s), "l"(g));
}

#define CP_COMMIT() asm volatile("cp.async.commit_group;")

#define LDSM_X4(R, addr)                                                     \
    asm volatile("ldmatrix.sync.aligned.m8n8.x4.shared.b16 {%0,%1,%2,%3}, [%4];" \
        : "=r"((R)[0]), "=r"((R)[1]), "=r"((R)[2]), "=r"((R)[3]) : "r"(addr))

#define LDSM_X4_T(R, addr)                                                   \
    asm volatile("ldmatrix.sync.aligned.m8n8.x4.trans.shared.b16 {%0,%1,%2,%3}, [%4];" \
        : "=r"((R)[0]), "=r"((R)[1]), "=r"((R)[2]), "=r"((R)[3]) : "r"(addr))

#define MMA16816(C, A, B0, B1)                                               \
    asm volatile("mma.sync.aligned.m16n8k16.row.col.f32.bf16.bf16.f32 "      \
        "{%0,%1,%2,%3}, {%4,%5,%6,%7}, {%8,%9}, {%0,%1,%2,%3};"              \
        : "+f"((C)[0]), "+f"((C)[1]), "+f"((C)[2]), "+f"((C)[3])             \
        : "r"((A)[0]), "r"((A)[1]), "r"((A)[2]), "r"((A)[3]),                \
          "r"(B0), "r"(B1))

__device__ __forceinline__ uint32_t pack_bf2(__nv_bfloat16 lo, __nv_bfloat16 hi) {
    unsigned short a = __bfloat16_as_ushort(lo);
    unsigned short b = __bfloat16_as_ushort(hi);
    return (uint32_t)a | ((uint32_t)b << 16);
}

// split two fp32 into packed bf16 hi-part and lo-residual-part regs
__device__ __forceinline__ void split_pack(float a, float b, uint32_t& hp, uint32_t& lp) {
    __nv_bfloat16 ha = __float2bfloat16(a);
    __nv_bfloat16 hb = __float2bfloat16(b);
    __nv_bfloat16 la = __float2bfloat16(a - __bfloat162float(ha));
    __nv_bfloat16 lb = __float2bfloat16(b - __bfloat162float(hb));
    hp = pack_bf2(ha, hb);
    lp = pack_bf2(la, lb);
}

// ---------------------------------------------------------------------------
// fp32 -> (bf16 hi, bf16 lo) split; float4 per thread
// ---------------------------------------------------------------------------
__global__ __launch_bounds__(256) void split_kernel(
    const float* __restrict__ s, __nv_bfloat16* __restrict__ hi,
    __nv_bfloat16* __restrict__ lo, int n4)
{
    int i = blockIdx.x * blockDim.x + threadIdx.x;
    if (i >= n4) return;
    float4 v = ((const float4*)s)[i];
    uint32_t h0, l0, h1, l1;
    split_pack(v.x, v.y, h0, l0);
    split_pack(v.z, v.w, h1, l1);
    ((uint32_t*)hi)[2 * i]     = h0;
    ((uint32_t*)hi)[2 * i + 1] = h1;
    ((uint32_t*)lo)[2 * i]     = l0;
    ((uint32_t*)lo)[2 * i + 1] = l1;
}

// ---------------------------------------------------------------------------
// bf16x3 GEMM via mma.sync:  D[128x128] = (Ah+Al)[128xK] @ (Bh+Bl)[128xK]^T
// MODE 0: write q/k/v bf16 hi/lo arrays.  MODE 1: out = D + bias (fp32).
// 256 threads (8 warps: 4 M x 2 N), warp tile 32x64, K-chunk 32, 2-stage.
// ---------------------------------------------------------------------------
template <int MODE>
__global__ __launch_bounds__(256) void mma_gemm(
    const __nv_bfloat16* __restrict__ Ah, const __nv_bfloat16* __restrict__ Al,
    const __nv_bfloat16* __restrict__ Bh, const __nv_bfloat16* __restrict__ Bl,
    const float* __restrict__ bias, float* __restrict__ out)
{
    constexpr int ROWB  = 80;                 // bytes per smem row (40 bf16)
    constexpr int TILE  = 128 * ROWB;         // 10240 B
    constexpr int STAGE = 4 * TILE;           // Ah, Al, Bh, Bl
    constexpr int NCH   = KKG / 32;           // 16 K-chunks

    extern __shared__ char dsm[];
    const uint32_t sbase = smem_u32(dsm);

    const int tid  = threadIdx.x;
    const int lane = tid & 31;
    const int wid  = tid >> 5;
    const int mw   = wid & 3;                 // 0..3 -> M groups of 32
    const int nw   = wid >> 2;                // 0..1 -> N groups of 64
    const int rowBase = blockIdx.y * 128;
    const int colBase = blockIdx.x * 128;

    float acc[2][8][4];
    #pragma unroll
    for (int a = 0; a < 2; a++)
        #pragma unroll
        for (int b = 0; b < 8; b++)
            #pragma unroll
            for (int c = 0; c < 4; c++) acc[a][b][c] = 0.0f;

    const uint32_t aOff = (uint32_t)((mw * 32 + (lane & 15)) * ROWB + (lane >> 4) * 16);
    const int mi   = lane >> 3;
    const uint32_t bOff = (uint32_t)((nw * 64 + (mi >> 1) * 8 + (lane & 7)) * ROWB + (mi & 1) * 16);

    auto loadChunk = [&](int ch, int buf) {
        const uint32_t sb = sbase + buf * STAGE;
        #pragma unroll
        for (int rep = 0; rep < 2; rep++) {
            const int id  = tid * 2 + rep;
            const int r   = id >> 2;
            const int seg = id & 3;
            const uint32_t so = (uint32_t)(r * ROWB + seg * 16);
            const size_t  ga = (size_t)(rowBase + r) * KKG + ch * 32 + seg * 8;
            const size_t  gb = (size_t)(colBase + r) * KKG + ch * 32 + seg * 8;
            cp_async16(sb + so,            Ah + ga);
            cp_async16(sb + TILE + so,     Al + ga);
            cp_async16(sb + 2 * TILE + so, Bh + gb);
            cp_async16(sb + 3 * TILE + so, Bl + gb);
        }
    };

    loadChunk(0, 0);
    CP_COMMIT();

    for (int ch = 0; ch < NCH; ch++) {
        if (ch + 1 < NCH) {
            loadChunk(ch + 1, (ch + 1) & 1);
            CP_COMMIT();
            asm volatile("cp.async.wait_group 1;");
        } else {
            asm volatile("cp.async.wait_group 0;");
        }
        __syncthreads();

        const uint32_t st = sbase + (ch & 1) * STAGE;
        #pragma unroll
        for (int ks = 0; ks < 2; ks++) {
            const uint32_t ko = ks * 32;
            uint32_t ah[2][4], al[2][4], bb[4][4];
            #pragma unroll
            for (int mm = 0; mm < 2; mm++) {
                LDSM_X4(ah[mm], st + aOff + mm * (16 * ROWB) + ko);
                LDSM_X4(al[mm], st + TILE + aOff + mm * (16 * ROWB) + ko);
            }
            #pragma unroll
            for (int nb = 0; nb < 4; nb++)
                LDSM_X4(bb[nb], st + 2 * TILE + bOff + nb * (16 * ROWB) + ko);

            #pragma unroll
            for (int mm = 0; mm < 2; mm++)
                #pragma unroll
                for (int nf = 0; nf < 8; nf++) {
                    const uint32_t b0 = bb[nf >> 1][(nf & 1) * 2];
                    const uint32_t b1 = bb[nf >> 1][(nf & 1) * 2 + 1];
                    MMA16816(acc[mm][nf], ah[mm], b0, b1);
                    MMA16816(acc[mm][nf], al[mm], b0, b1);
                }

            #pragma unroll
            for (int nb = 0; nb < 4; nb++)
                LDSM_X4(bb[nb], st + 3 * TILE + bOff + nb * (16 * ROWB) + ko);

            #pragma unroll
            for (int mm = 0; mm < 2; mm++)
                #pragma unroll
                for (int nf = 0; nf < 8; nf++) {
                    const uint32_t b0 = bb[nf >> 1][(nf & 1) * 2];
                    const uint32_t b1 = bb[nf >> 1][(nf & 1) * 2 + 1];
                    MMA16816(acc[mm][nf], ah[mm], b0, b1);
                }
        }
        __syncthreads();
    }

    // Epilogue. C frag: rows lane/4 (+8), cols (lane%4)*2
    #pragma unroll
    for (int mm = 0; mm < 2; mm++) {
        #pragma unroll
        for (int nf = 0; nf < 8; nf++) {
            const int c = colBase + nw * 64 + nf * 8 + (lane & 3) * 2;
            const int r0 = rowBase + mw * 32 + mm * 16 + (lane >> 2);
            if (MODE == 0) {
                const int three = c >> 9;
                const int head  = (c >> 5) & 15;
                const int d     = c & 31;
                __nv_bfloat16* dh = (three == 0) ? g_qh : (three == 1) ? g_kh : g_vh;
                __nv_bfloat16* dl = (three == 0) ? g_ql : (three == 1) ? g_kl : g_vl;
                #pragma unroll
                for (int half = 0; half < 2; half++) {
                    const int r = r0 + half * 8;
                    const int b = r >> 10, n = r & 1023;
                    const size_t idx = (((size_t)(b * NHEAD + head) * NN) + n) * HD + d;
                    uint32_t hp, lp;
                    split_pack(acc[mm][nf][half * 2], acc[mm][nf][half * 2 + 1], hp, lp);
                    *(uint32_t*)(dh + idx) = hp;
                    *(uint32_t*)(dl + idx) = lp;
                }
            } else {
                const float2 bv = *(const float2*)(bias + c);
                #pragma unroll
                for (int half = 0; half < 2; half++) {
                    const int r = r0 + half * 8;
                    float2 v = make_float2(acc[mm][nf][half * 2] + bv.x,
                                           acc[mm][nf][half * 2 + 1] + bv.y);
                    *(float2*)(out + (size_t)r * CD + c) = v;
                }
            }
        }
    }
}

// ---------------------------------------------------------------------------
// Tensor-core flash attention (bf16 hi/lo splits, fp32 softmax).
// Block: 256 thr / 8 warps; 128 q-rows per block, 16 per warp.
// Keys in 64-wide double-buffered tiles (stride-80B rows).
// grid = (NN/128, NHEAD, BB)
// ---------------------------------------------------------------------------
__global__ __launch_bounds__(256) void attn_mma_kernel(float* __restrict__ y)
{
    constexpr int ROWB   = 80;
    constexpr int QBYTES = 128 * ROWB;        // 10240 per matrix
    constexpr int TMAT   = 64 * ROWB;         // 5120 per kv matrix
    constexpr int STAGE  = 4 * TMAT;          // kh, kl, vh, vl
    const float SC = 0.17677669529663687f;    // 32^-0.5

    extern __shared__ char dsm[];
    const uint32_t sQH = smem_u32(dsm);
    const uint32_t sQL = sQH + QBYTES;
    const uint32_t sKV = sQH + 2 * QBYTES;    // stage base

    const int tid  = threadIdx.x;
    const int lane = tid & 31;
    const int wid  = tid >> 5;
    const int wr   = wid * 16;                // warp's q-row offset within block

    const int b = blockIdx.z;
    const int h = blockIdx.y;
    const int rowBase = blockIdx.x * 128;
    const size_t hb = ((size_t)(b * NHEAD + h)) * NN * HD;

    // ---- async loads: Q (once) + KV tile loader ----
    {   // Q: 2 matrices x 128 rows x 4 segs = 1024 cp / 256 thr
        #pragma unroll
        for (int rep = 0; rep < 2; rep++) {
            const int id  = tid * 2 + rep;
            const int row = id >> 2, seg = id & 3;
            const uint32_t so = (uint32_t)(row * ROWB + seg * 16);
            const size_t g = hb + (size_t)(rowBase + row) * HD + seg * 8;
            cp_async16(sQH + so, g_qh + g);
            cp_async16(sQL + so, g_ql + g);
        }
    }
    auto loadKV = [&](int t, int buf) {
        const uint32_t sb = sKV + buf * STAGE;
        const int row = tid >> 2, seg = tid & 3;       // 64 rows x 4 segs = 256
        const uint32_t so = (uint32_t)(row * ROWB + seg * 16);
        const size_t g = hb + (size_t)(t * 64 + row) * HD + seg * 8;
        cp_async16(sb + so,            g_kh + g);
        cp_async16(sb + TMAT + so,     g_kl + g);
        cp_async16(sb + 2 * TMAT + so, g_vh + g);
        cp_async16(sb + 3 * TMAT + so, g_vl + g);
    };

    loadKV(0, 0);
    CP_COMMIT();

    // per-thread state
    float acc[4][4];
    #pragma unroll
    for (int a = 0; a < 4; a++)
        #pragma unroll
        for (int c = 0; c < 4; c++) acc[a][c] = 0.0f;
    float m0 = -1e30f, m1 = -1e30f, l0 = 0.0f, l1 = 0.0f;

    uint32_t qh[2][4], ql[2][4];
    const uint32_t qOff = (uint32_t)((wr + (lane & 15)) * ROWB + (lane >> 4) * 16);
    const uint32_t kOff = (uint32_t)((lane & 7) * ROWB + (lane >> 3) * 16);
    const uint32_t vOff = (uint32_t)((((lane >> 3) & 1) * 8 + (lane & 7)) * ROWB
                                     + ((lane >> 4) * 8) * 2);

    for (int t = 0; t < NN / 64; t++) {
        if (t + 1 < NN / 64) {
            loadKV(t + 1, (t + 1) & 1);
            CP_COMMIT();
            asm volatile("cp.async.wait_group 1;");
        } else {
            asm volatile("cp.async.wait_group 0;");
        }
        __syncthreads();

        if (t == 0) {   // Q fragments (ready: group containing Q completed)
            #pragma unroll
            for (int kt = 0; kt < 2; kt++) {
                LDSM_X4(qh[kt], sQH + qOff + kt * 32);
                LDSM_X4(ql[kt], sQL + qOff + kt * 32);
            }
        }

        const uint32_t st = sKV + (t & 1) * STAGE;

        // ---- scores: S = (Qh+Ql)·(Kh+Kl)^T (3 splits) ----
        float s[8][4];
        #pragma unroll
        for (int j = 0; j < 8; j++) {
            uint32_t kf[4], lf[4];
            LDSM_X4(kf, st + j * (8 * ROWB) + kOff);
            LDSM_X4(lf, st + TMAT + j * (8 * ROWB) + kOff);
            s[j][0] = s[j][1] = s[j][2] = s[j][3] = 0.0f;
            MMA16816(s[j], qh[0], kf[0], kf[1]);
            MMA16816(s[j], qh[1], kf[2], kf[3]);
            MMA16816(s[j], qh[0], lf[0], lf[1]);
            MMA16816(s[j], qh[1], lf[2], lf[3]);
            MMA16816(s[j], ql[0], kf[0], kf[1]);
            MMA16816(s[j], ql[1], kf[2], kf[3]);
        }

        // ---- online softmax (rows r0 = lane/4, r1 = r0+8) ----
        float mx0 = -1e30f, mx1 = -1e30f;
        #pragma unroll
        for (int j = 0; j < 8; j++) {
            mx0 = fmaxf(mx0, fmaxf(s[j][0], s[j][1]));
            mx1 = fmaxf(mx1, fmaxf(s[j][2], s[j][3]));
        }
        mx0 = fmaxf(mx0, __shfl_xor_sync(0xffffffffu, mx0, 1));
        mx0 = fmaxf(mx0, __shfl_xor_sync(0xffffffffu, mx0, 2));
        mx1 = fmaxf(mx1, __shfl_xor_sync(0xffffffffu, mx1, 1));
        mx1 = fmaxf(mx1, __shfl_xor_sync(0xffffffffu, mx1, 2));
        const float nm0 = fmaxf(m0, mx0), nm1 = fmaxf(m1, mx1);
        const float cf0 = __expf((m0 - nm0) * SC);
        const float cf1 = __expf((m1 - nm1) * SC);
        m0 = nm0; m1 = nm1;
        const float ms0 = m0 * SC, ms1 = m1 * SC;
        float ps0 = 0.0f, ps1 = 0.0f;
        #pragma unroll
        for (int j = 0; j < 8; j++) {
            s[j][0] = __expf(fmaf(s[j][0], SC, -ms0));
            s[j][1] = __expf(fmaf(s[j][1], SC, -ms0));
            s[j][2] = __expf(fmaf(s[j][2], SC, -ms1));
            s[j][3] = __expf(fmaf(s[j][3], SC, -ms1));
            ps0 += s[j][0] + s[j][1];
            ps1 += s[j][2] + s[j][3];
        }
        l0 = l0 * cf0 + ps0;
        l1 = l1 * cf1 + ps1;
        #pragma unroll
        for (int a = 0; a < 4; a++) {
            acc[a][0] *= cf0; acc[a][1] *= cf0;
            acc[a][2] *= cf1; acc[a][3] *= cf1;
        }

        // ---- P·V (P register-resident, 3 splits) ----
        #pragma unroll
        for (int kk = 0; kk < 4; kk++) {
            uint32_t ph[4], pl[4];
            split_pack(s[2 * kk][0],     s[2 * kk][1],     ph[0], pl[0]);
            split_pack(s[2 * kk][2],     s[2 * kk][3],     ph[1], pl[1]);
            split_pack(s[2 * kk + 1][0], s[2 * kk + 1][1], ph[2], pl[2]);
            split_pack(s[2 * kk + 1][2], s[2 * kk + 1][3], ph[3], pl[3]);
            #pragma unroll
            for (int dp = 0; dp < 2; dp++) {
                uint32_t vh[4], vl[4];
                const uint32_t va = st + (uint32_t)(kk * 16) * ROWB + vOff + dp * 32;
                LDSM_X4_T(vh, 2 * TMAT + va);
                LDSM_X4_T(vl, 3 * TMAT + va);
                MMA16816(acc[2 * dp],     ph, vh[0], vh[1]);
                MMA16816(acc[2 * dp + 1], ph, vh[2], vh[3]);
                MMA16816(acc[2 * dp],     pl, vh[0], vh[1]);
                MMA16816(acc[2 * dp + 1], pl, vh[2], vh[3]);
                MMA16816(acc[2 * dp],     ph, vl[0], vl[1]);
                MMA16816(acc[2 * dp + 1], ph, vl[2], vl[3]);
            }
        }
        __syncthreads();
    }

    // ---- finalize ----
    l0 += __shfl_xor_sync(0xffffffffu, l0, 1);
    l0 += __shfl_xor_sync(0xffffffffu, l0, 2);
    l1 += __shfl_xor_sync(0xffffffffu, l1, 1);
    l1 += __shfl_xor_sync(0xffffffffu, l1, 2);
    const float inv0 = 1.0f / l0, inv1 = 1.0f / l1;

    const int r0 = rowBase + wr + (lane >> 2);
    const int cB = h * HD + (lane & 3) * 2;
    #pragma unroll
    for (int dn = 0; dn < 4; dn++) {
        *(float2*)(y + (size_t)(b * NN + r0) * CD + cB + dn * 8) =
            make_float2(acc[dn][0] * inv0, acc[dn][1] * inv0);
        *(float2*)(y + (size_t)(b * NN + r0 + 8) * CD + cB + dn * 8) =
            make_float2(acc[dn][2] * inv1, acc[dn][3] * inv1);
    }
}

// ---------------------------------------------------------------------------
// LePE depthwise 5x5 conv, channels-last; y += conv(x) + bias
// ---------------------------------------------------------------------------
__global__ __launch_bounds__(128) void lepe_kernel(
    const float* __restrict__ x, const float* __restrict__ wl,
    const float* __restrict__ bl, float* __restrict__ y)
{
    const int b  = blockIdx.z;
    const int yy = blockIdx.y;
    const int xx = blockIdx.x;
    const int c  = threadIdx.x * 4;

    float4 sum = *(const float4*)&bl[c];
    #pragma unroll
    for (int ky = 0; ky < 5; ky++) {
        const int iy = yy + ky - 2;
        if (iy < 0 || iy >= HH) continue;
        #pragma unroll
        for (int kx = 0; kx < 5; kx++) {
            const int ix = xx + kx - 2;
            if (ix < 0 || ix >= WWI) continue;
            const float4 xv = *(const float4*)&x[(((size_t)(b * HH + iy) * WWI + ix) * CD) + c];
            const int wk = ky * 5 + kx;
            sum.x = fmaf(xv.x, wl[(c + 0) * 25 + wk], sum.x);
            sum.y = fmaf(xv.y, wl[(c + 1) * 25 + wk], sum.y);
            sum.z = fmaf(xv.z, wl[(c + 2) * 25 + wk], sum.z);
            sum.w = fmaf(xv.w, wl[(c + 3) * 25 + wk], sum.w);
        }
    }
    float* yp = &y[(((size_t)b * NN + yy * WWI + xx) * CD) + c];
    float4 cur = *(float4*)yp;
    cur.x += sum.x; cur.y += sum.y; cur.z += sum.z; cur.w += sum.w;
    *(float4*)yp = cur;
}

// ---------------------------------------------------------------------------
extern "C" void kernel_launch(void* const* d_in, const int* in_sizes, int n_in,
                              void* d_out, int out_size)
{
    const float* x      = (const float*)d_in[0];
    const float* w_qkv  = (const float*)d_in[1];
    const float* w_proj = (const float*)d_in[2];
    const float* b_proj = (const float*)d_in[3];
    const float* w_lepe = (const float*)d_in[4];
    const float* b_lepe = (const float*)d_in[5];
    float* out = (float*)d_out;

    float *yPtr;
    __nv_bfloat16 *xh, *xl, *yh, *yl, *wqh, *wql, *wph, *wpl;
    cudaGetSymbolAddress((void**)&yPtr, g_y);
    cudaGetSymbolAddress((void**)&xh, g_xh);   cudaGetSymbolAddress((void**)&xl, g_xl);
    cudaGetSymbolAddress((void**)&yh, g_yh);   cudaGetSymbolAddress((void**)&yl, g_yl);
    cudaGetSymbolAddress((void**)&wqh, g_wqh); cudaGetSymbolAddress((void**)&wql, g_wql);
    cudaGetSymbolAddress((void**)&wph, g_wph); cudaGetSymbolAddress((void**)&wpl, g_wpl);

    constexpr int SMEM_GEMM = 2 * 4 * 128 * 80;            // 81920 B
    constexpr int SMEM_ATTN = 2 * 128 * 80 + 2 * 4 * 64 * 80;  // 20480 + 40960 = 61440 B
    cudaFuncSetAttribute(mma_gemm<0>, cudaFuncAttributeMaxDynamicSharedMemorySize, SMEM_GEMM);
    cudaFuncSetAttribute(mma_gemm<1>, cudaFuncAttributeMaxDynamicSharedMemorySize, SMEM_GEMM);
    cudaFuncSetAttribute(attn_mma_kernel, cudaFuncAttributeMaxDynamicSharedMemorySize, SMEM_ATTN);

    // 0) split inputs/weights to bf16 hi/lo
    {
        int n4 = MTOT * CD / 4;
        split_kernel<<<(n4 + 255) / 256, 256>>>(x, xh, xl, n4);
        int w4 = 3 * CD * CD / 4;
        split_kernel<<<(w4 + 255) / 256, 256>>>(w_qkv, wqh, wql, w4);
        int p4 = CD * CD / 4;
        split_kernel<<<(p4 + 255) / 256, 256>>>(w_proj, wph, wpl, p4);
    }
    // 1) QKV projection -> g_{q,k,v}{h,l}   (M=8192, N=1536, K=512)
    {
        dim3 grid(3 * CD / 128, MTOT / 128);
        mma_gemm<0><<<grid, 256, SMEM_GEMM>>>(xh, xl, wqh, wql, nullptr, nullptr);
    }
    // 2) Attention -> g_y
    {
        dim3 grid(NN / 128, NHEAD, BB);
        attn_mma_kernel<<<grid, 256, SMEM_ATTN>>>(yPtr);
    }
    // 3) LePE: g_y += dwconv(x)
    {
        dim3 grid(WWI, HH, BB);
        lepe_kernel<<<grid, 128>>>(x, w_lepe, b_lepe, yPtr);
    }
    // 4) split y, then output projection -> d_out  (M=8192, N=512, K=512)
    {
        int n4 = MTOT * CD / 4;
        split_kernel<<<(n4 + 255) / 256, 256>>>(yPtr, yh, yl, n4);
        dim3 grid(CD / 128, MTOT / 128);
        mma_gemm<1><<<grid, 256, SMEM_GEMM>>>(yh, yl, wph, wpl, b_proj, out);
    }
}

// round 5
// speedup vs baseline: 2.7523x; 1.7656x over previous
#include <cuda_runtime.h>
#include <cuda_bf16.h>
#include <cstdint>

// Problem constants
constexpr int BB    = 8;      // batch
constexpr int HH    = 32;     // height
constexpr int WWI   = 32;     // width
constexpr int NN    = 1024;   // tokens = H*W
constexpr int CD    = 512;    // dim
constexpr int NHEAD = 16;
constexpr int HD    = 32;     // head dim
constexpr int MTOT  = BB * NN;   // 8192 rows
constexpr int KKG   = 512;       // GEMM K (both GEMMs)

// ---------------------------------------------------------------------------
// Scratch (device globals; no allocation allowed)
// ---------------------------------------------------------------------------
__device__ float g_y[MTOT * CD];                    // attn out (fp32)
__device__ __nv_bfloat16 g_xh[MTOT * CD],  g_xl[MTOT * CD];
__device__ __nv_bfloat16 g_yh[MTOT * CD],  g_yl[MTOT * CD];
__device__ __nv_bfloat16 g_wqh[3 * CD * CD], g_wql[3 * CD * CD];
__device__ __nv_bfloat16 g_wph[CD * CD],     g_wpl[CD * CD];
// Q/K/V in bf16 hi/lo, layout [(b*NHEAD+h)][N][HD]
constexpr int QKV_ELEMS = BB * NHEAD * NN * HD;
__device__ __nv_bfloat16 g_qh[QKV_ELEMS], g_ql[QKV_ELEMS];
__device__ __nv_bfloat16 g_kh[QKV_ELEMS], g_kl[QKV_ELEMS];
__device__ __nv_bfloat16 g_vh[QKV_ELEMS], g_vl[QKV_ELEMS];

// ---------------------------------------------------------------------------
// PTX helpers — sm_103-base ISA only (NO tcgen05: harness PTX targets sm_103)
// ---------------------------------------------------------------------------
__device__ __forceinline__ uint32_t smem_u32(const void* p) {
    uint32_t a;
    asm("{ .reg .u64 t; cvta.to.shared.u64 t, %1; cvt.u32.u64 %0, t; }" : "=r"(a) : "l"(p));
    return a;
}

__device__ __forceinline__ void cp_async16(uint32_t s, const void* g) {
    asm volatile("cp.async.cg.shared.global [%0], [%1], 16;" :: "r"(s), "l"(g));
}

#define CP_COMMIT() asm volatile("cp.async.commit_group;")

#define LDSM_X4(R, addr)                                                     \
    asm volatile("ldmatrix.sync.aligned.m8n8.x4.shared.b16 {%0,%1,%2,%3}, [%4];" \
        : "=r"((R)[0]), "=r"((R)[1]), "=r"((R)[2]), "=r"((R)[3]) : "r"(addr))

#define LDSM_X4_T(R, addr)                                                   \
    asm volatile("ldmatrix.sync.aligned.m8n8.x4.trans.shared.b16 {%0,%1,%2,%3}, [%4];" \
        : "=r"((R)[0]), "=r"((R)[1]), "=r"((R)[2]), "=r"((R)[3]) : "r"(addr))

#define MMA16816(C, A, B0, B1)                                               \
    asm volatile("mma.sync.aligned.m16n8k16.row.col.f32.bf16.bf16.f32 "      \
        "{%0,%1,%2,%3}, {%4,%5,%6,%7}, {%8,%9}, {%0,%1,%2,%3};"              \
        : "+f"((C)[0]), "+f"((C)[1]), "+f"((C)[2]), "+f"((C)[3])             \
        : "r"((A)[0]), "r"((A)[1]), "r"((A)[2]), "r"((A)[3]),                \
          "r"(B0), "r"(B1))

// SW64 swizzle: 64B rows, 16B segments; conflict-free for ldmatrix + cp.async
__device__ __forceinline__ uint32_t sw64(int row, int seg) {
    return (uint32_t)(row * 64 + ((seg ^ ((row >> 1) & 3)) << 4));
}

__device__ __forceinline__ uint32_t pack_bf2(__nv_bfloat16 lo, __nv_bfloat16 hi) {
    unsigned short a = __bfloat16_as_ushort(lo);
    unsigned short b = __bfloat16_as_ushort(hi);
    return (uint32_t)a | ((uint32_t)b << 16);
}

__device__ __forceinline__ void split_pack(float a, float b, uint32_t& hp, uint32_t& lp) {
    __nv_bfloat16 ha = __float2bfloat16(a);
    __nv_bfloat16 hb = __float2bfloat16(b);
    __nv_bfloat16 la = __float2bfloat16(a - __bfloat162float(ha));
    __nv_bfloat16 lb = __float2bfloat16(b - __bfloat162float(hb));
    hp = pack_bf2(ha, hb);
    lp = pack_bf2(la, lb);
}

// ---------------------------------------------------------------------------
// fp32 -> (bf16 hi, bf16 lo) split; float4 per thread
// ---------------------------------------------------------------------------
__global__ __launch_bounds__(256) void split_kernel(
    const float* __restrict__ s, __nv_bfloat16* __restrict__ hi,
    __nv_bfloat16* __restrict__ lo, int n4)
{
    int i = blockIdx.x * blockDim.x + threadIdx.x;
    if (i >= n4) return;
    float4 v = ((const float4*)s)[i];
    uint32_t h0, l0, h1, l1;
    split_pack(v.x, v.y, h0, l0);
    split_pack(v.z, v.w, h1, l1);
    ((uint32_t*)hi)[2 * i]     = h0;
    ((uint32_t*)hi)[2 * i + 1] = h1;
    ((uint32_t*)lo)[2 * i]     = l0;
    ((uint32_t*)lo)[2 * i + 1] = l1;
}

// ---------------------------------------------------------------------------
// bf16x3 GEMM via mma.sync:  D[128x128] = (Ah+Al)[128xK] @ (Bh+Bl)[128xK]^T
// MODE 0: write q/k/v bf16 hi/lo arrays.  MODE 1: out = D + bias (fp32).
// 256 threads (8 warps: 4 M x 2 N), warp tile 32x64, K-chunk 32, 2-stage,
// SW64-swizzled 64B smem rows. 2 CTAs/SM.
// ---------------------------------------------------------------------------
template <int MODE>
__global__ __launch_bounds__(256, 2) void mma_gemm(
    const __nv_bfloat16* __restrict__ Ah, const __nv_bfloat16* __restrict__ Al,
    const __nv_bfloat16* __restrict__ Bh, const __nv_bfloat16* __restrict__ Bl,
    const float* __restrict__ bias, float* __restrict__ out)
{
    constexpr int TILE  = 128 * 64;           // 8192 B
    constexpr int STAGE = 4 * TILE;           // 32768 B: Ah, Al, Bh, Bl
    constexpr int NCH   = KKG / 32;           // 16 K-chunks

    extern __shared__ char dsm[];
    const uint32_t sbase = smem_u32(dsm);

    const int tid  = threadIdx.x;
    const int lane = tid & 31;
    const int wid  = tid >> 5;
    const int mw   = wid & 3;                 // 0..3 -> M groups of 32
    const int nw   = wid >> 2;                // 0..1 -> N groups of 64
    const int rowBase = blockIdx.y * 128;
    const int colBase = blockIdx.x * 128;

    float acc[2][8][4];
    #pragma unroll
    for (int a = 0; a < 2; a++)
        #pragma unroll
        for (int b = 0; b < 8; b++)
            #pragma unroll
            for (int c = 0; c < 4; c++) acc[a][b][c] = 0.0f;

    const int aRow  = mw * 32 + (lane & 15);
    const int aSeg0 = lane >> 4;
    const int bRow  = nw * 64 + ((lane >> 4) & 1) * 8 + (lane & 7);
    const int bSeg0 = (lane >> 3) & 1;

    auto loadChunk = [&](int ch, int buf) {
        const uint32_t sb = sbase + buf * STAGE;
        #pragma unroll
        for (int rep = 0; rep < 2; rep++) {
            const int id  = tid * 2 + rep;
            const int r   = id >> 2;
            const int seg = id & 3;
            const uint32_t so = sw64(r, seg);
            const size_t  ga = (size_t)(rowBase + r) * KKG + ch * 32 + seg * 8;
            const size_t  gb = (size_t)(colBase + r) * KKG + ch * 32 + seg * 8;
            cp_async16(sb + so,            Ah + ga);
            cp_async16(sb + TILE + so,     Al + ga);
            cp_async16(sb + 2 * TILE + so, Bh + gb);
            cp_async16(sb + 3 * TILE + so, Bl + gb);
        }
    };

    loadChunk(0, 0);
    CP_COMMIT();

    for (int ch = 0; ch < NCH; ch++) {
        if (ch + 1 < NCH) {
            loadChunk(ch + 1, (ch + 1) & 1);
            CP_COMMIT();
            asm volatile("cp.async.wait_group 1;");
        } else {
            asm volatile("cp.async.wait_group 0;");
        }
        __syncthreads();

        const uint32_t st = sbase + (ch & 1) * STAGE;
        #pragma unroll
        for (int ks = 0; ks < 2; ks++) {
            uint32_t ah[2][4], al[2][4], bb[4][4];
            #pragma unroll
            for (int mm = 0; mm < 2; mm++) {
                const uint32_t ad = st + sw64(aRow + mm * 16, aSeg0 + 2 * ks);
                LDSM_X4(ah[mm], ad);
                LDSM_X4(al[mm], ad + TILE);
            }
            #pragma unroll
            for (int nb = 0; nb < 4; nb++)
                LDSM_X4(bb[nb], st + 2 * TILE + sw64(bRow + nb * 16, bSeg0 + 2 * ks));

            #pragma unroll
            for (int mm = 0; mm < 2; mm++)
                #pragma unroll
                for (int nf = 0; nf < 8; nf++) {
                    const uint32_t b0 = bb[nf >> 1][(nf & 1) * 2];
                    const uint32_t b1 = bb[nf >> 1][(nf & 1) * 2 + 1];
                    MMA16816(acc[mm][nf], ah[mm], b0, b1);
                    MMA16816(acc[mm][nf], al[mm], b0, b1);
                }

            #pragma unroll
            for (int nb = 0; nb < 4; nb++)
                LDSM_X4(bb[nb], st + 3 * TILE + sw64(bRow + nb * 16, bSeg0 + 2 * ks));

            #pragma unroll
            for (int mm = 0; mm < 2; mm++)
                #pragma unroll
                for (int nf = 0; nf < 8; nf++) {
                    const uint32_t b0 = bb[nf >> 1][(nf & 1) * 2];
                    const uint32_t b1 = bb[nf >> 1][(nf & 1) * 2 + 1];
                    MMA16816(acc[mm][nf], ah[mm], b0, b1);
                }
        }
        __syncthreads();
    }

    // Epilogue. C frag: rows lane/4 (+8), cols (lane%4)*2
    #pragma unroll
    for (int mm = 0; mm < 2; mm++) {
        #pragma unroll
        for (int nf = 0; nf < 8; nf++) {
            const int c = colBase + nw * 64 + nf * 8 + (lane & 3) * 2;
            const int r0 = rowBase + mw * 32 + mm * 16 + (lane >> 2);
            if (MODE == 0) {
                const int three = c >> 9;
                const int head  = (c >> 5) & 15;
                const int d     = c & 31;
                __nv_bfloat16* dh = (three == 0) ? g_qh : (three == 1) ? g_kh : g_vh;
                __nv_bfloat16* dl = (three == 0) ? g_ql : (three == 1) ? g_kl : g_vl;
                #pragma unroll
                for (int half = 0; half < 2; half++) {
                    const int r = r0 + half * 8;
                    const int b = r >> 10, n = r & 1023;
                    const size_t idx = (((size_t)(b * NHEAD + head) * NN) + n) * HD + d;
                    uint32_t hp, lp;
                    split_pack(acc[mm][nf][half * 2], acc[mm][nf][half * 2 + 1], hp, lp);
                    *(uint32_t*)(dh + idx) = hp;
                    *(uint32_t*)(dl + idx) = lp;
                }
            } else {
                const float2 bv = *(const float2*)(bias + c);
                #pragma unroll
                for (int half = 0; half < 2; half++) {
                    const int r = r0 + half * 8;
                    float2 v = make_float2(acc[mm][nf][half * 2] + bv.x,
                                           acc[mm][nf][half * 2 + 1] + bv.y);
                    *(float2*)(out + (size_t)r * CD + c) = v;
                }
            }
        }
    }
}

// ---------------------------------------------------------------------------
// Tensor-core flash attention (bf16 hi/lo splits, fp32 softmax).
// 256 thr / 8 warps; 128 q-rows per block, 16 per warp; 64-key tiles,
// 2-stage cp.async, SW64 swizzle. 2 CTAs/SM. grid = (NN/128, NHEAD, BB)
// ---------------------------------------------------------------------------
__global__ __launch_bounds__(256, 2) void attn_mma_kernel(float* __restrict__ y)
{
    constexpr int QBYTES = 128 * 64;          // 8192 per matrix
    constexpr int TMAT   = 64 * 64;           // 4096 per kv matrix
    constexpr int STAGE  = 4 * TMAT;          // 16384: kh, kl, vh, vl
    const float SC = 0.17677669529663687f;    // 32^-0.5

    extern __shared__ char dsm[];
    const uint32_t sQH = smem_u32(dsm);
    const uint32_t sKV = sQH + 2 * QBYTES;

    const int tid  = threadIdx.x;
    const int lane = tid & 31;
    const int wid  = tid >> 5;
    const int wr   = wid * 16;

    const int b = blockIdx.z;
    const int h = blockIdx.y;
    const int rowBase = blockIdx.x * 128;
    const size_t hb = ((size_t)(b * NHEAD + h)) * NN * HD;

    {   // Q: 2 matrices x 128 rows x 4 segs
        #pragma unroll
        for (int rep = 0; rep < 2; rep++) {
            const int id  = tid * 2 + rep;
            const int row = id >> 2, seg = id & 3;
            const uint32_t so = sw64(row, seg);
            const size_t g = hb + (size_t)(rowBase + row) * HD + seg * 8;
            cp_async16(sQH + so,          g_qh + g);
            cp_async16(sQH + QBYTES + so, g_ql + g);
        }
    }
    auto loadKV = [&](int t, int buf) {
        const uint32_t sb = sKV + buf * STAGE;
        const int row = tid >> 2, seg = tid & 3;
        const uint32_t so = sw64(row, seg);
        const size_t g = hb + (size_t)(t * 64 + row) * HD + seg * 8;
        cp_async16(sb + so,            g_kh + g);
        cp_async16(sb + TMAT + so,     g_kl + g);
        cp_async16(sb + 2 * TMAT + so, g_vh + g);
        cp_async16(sb + 3 * TMAT + so, g_vl + g);
    };

    loadKV(0, 0);
    CP_COMMIT();

    float acc[4][4];
    #pragma unroll
    for (int a = 0; a < 4; a++)
        #pragma unroll
        for (int c = 0; c < 4; c++) acc[a][c] = 0.0f;
    float m0 = -1e30f, m1 = -1e30f, l0 = 0.0f, l1 = 0.0f;

    uint32_t qh[2][4], ql[2][4];
    const int qRow = wr + (lane & 15);
    const int qSeg0 = lane >> 4;
    const int kRowL = lane & 7;               // + j*8
    const int kSeg = lane >> 3;
    const int vRowL = ((lane >> 3) & 1) * 8 + (lane & 7);   // + kk*16
    const int vSeg0 = lane >> 4;              // + 2*dp

    for (int t = 0; t < NN / 64; t++) {
        if (t + 1 < NN / 64) {
            loadKV(t + 1, (t + 1) & 1);
            CP_COMMIT();
            asm volatile("cp.async.wait_group 1;");
        } else {
            asm volatile("cp.async.wait_group 0;");
        }
        __syncthreads();

        if (t == 0) {
            #pragma unroll
            for (int kt = 0; kt < 2; kt++) {
                const uint32_t qa = sQH + sw64(qRow, qSeg0 + 2 * kt);
                LDSM_X4(qh[kt], qa);
                LDSM_X4(ql[kt], qa + QBYTES);
            }
        }

        const uint32_t st = sKV + (t & 1) * STAGE;

        // ---- scores: S = (Qh+Ql)·(Kh+Kl)^T ----
        float s[8][4];
        #pragma unroll
        for (int j = 0; j < 8; j++) {
            uint32_t kf[4], lf[4];
            const uint32_t ka = st + sw64(j * 8 + kRowL, kSeg);
            LDSM_X4(kf, ka);
            LDSM_X4(lf, ka + TMAT);
            s[j][0] = s[j][1] = s[j][2] = s[j][3] = 0.0f;
            MMA16816(s[j], qh[0], kf[0], kf[1]);
            MMA16816(s[j], qh[1], kf[2], kf[3]);
            MMA16816(s[j], qh[0], lf[0], lf[1]);
            MMA16816(s[j], qh[1], lf[2], lf[3]);
            MMA16816(s[j], ql[0], kf[0], kf[1]);
            MMA16816(s[j], ql[1], kf[2], kf[3]);
        }

        // ---- online softmax ----
        float mx0 = -1e30f, mx1 = -1e30f;
        #pragma unroll
        for (int j = 0; j < 8; j++) {
            mx0 = fmaxf(mx0, fmaxf(s[j][0], s[j][1]));
            mx1 = fmaxf(mx1, fmaxf(s[j][2], s[j][3]));
        }
        mx0 = fmaxf(mx0, __shfl_xor_sync(0xffffffffu, mx0, 1));
        mx0 = fmaxf(mx0, __shfl_xor_sync(0xffffffffu, mx0, 2));
        mx1 = fmaxf(mx1, __shfl_xor_sync(0xffffffffu, mx1, 1));
        mx1 = fmaxf(mx1, __shfl_xor_sync(0xffffffffu, mx1, 2));
        const float nm0 = fmaxf(m0, mx0), nm1 = fmaxf(m1, mx1);
        const float cf0 = __expf((m0 - nm0) * SC);
        const float cf1 = __expf((m1 - nm1) * SC);
        m0 = nm0; m1 = nm1;
        const float ms0 = m0 * SC, ms1 = m1 * SC;
        float ps0 = 0.0f, ps1 = 0.0f;
        #pragma unroll
        for (int j = 0; j < 8; j++) {
            s[j][0] = __expf(fmaf(s[j][0], SC, -ms0));
            s[j][1] = __expf(fmaf(s[j][1], SC, -ms0));
            s[j][2] = __expf(fmaf(s[j][2], SC, -ms1));
            s[j][3] = __expf(fmaf(s[j][3], SC, -ms1));
            ps0 += s[j][0] + s[j][1];
            ps1 += s[j][2] + s[j][3];
        }
        l0 = l0 * cf0 + ps0;
        l1 = l1 * cf1 + ps1;
        #pragma unroll
        for (int a = 0; a < 4; a++) {
            acc[a][0] *= cf0; acc[a][1] *= cf0;
            acc[a][2] *= cf1; acc[a][3] *= cf1;
        }

        // ---- P·V (P register-resident) ----
        #pragma unroll
        for (int kk = 0; kk < 4; kk++) {
            uint32_t ph[4], pl[4];
            split_pack(s[2 * kk][0],     s[2 * kk][1],     ph[0], pl[0]);
            split_pack(s[2 * kk][2],     s[2 * kk][3],     ph[1], pl[1]);
            split_pack(s[2 * kk + 1][0], s[2 * kk + 1][1], ph[2], pl[2]);
            split_pack(s[2 * kk + 1][2], s[2 * kk + 1][3], ph[3], pl[3]);
            #pragma unroll
            for (int dp = 0; dp < 2; dp++) {
                uint32_t vh[4], vl[4];
                const uint32_t va = st + 2 * TMAT + sw64(kk * 16 + vRowL, vSeg0 + 2 * dp);
                LDSM_X4_T(vh, va);
                LDSM_X4_T(vl, va + TMAT);
                MMA16816(acc[2 * dp],     ph, vh[0], vh[1]);
                MMA16816(acc[2 * dp + 1], ph, vh[2], vh[3]);
                MMA16816(acc[2 * dp],     pl, vh[0], vh[1]);
                MMA16816(acc[2 * dp + 1], pl, vh[2], vh[3]);
                MMA16816(acc[2 * dp],     ph, vl[0], vl[1]);
                MMA16816(acc[2 * dp + 1], ph, vl[2], vl[3]);
            }
        }
        __syncthreads();
    }

    l0 += __shfl_xor_sync(0xffffffffu, l0, 1);
    l0 += __shfl_xor_sync(0xffffffffu, l0, 2);
    l1 += __shfl_xor_sync(0xffffffffu, l1, 1);
    l1 += __shfl_xor_sync(0xffffffffu, l1, 2);
    const float inv0 = 1.0f / l0, inv1 = 1.0f / l1;

    const int r0 = rowBase + wr + (lane >> 2);
    const int cB = h * HD + (lane & 3) * 2;
    #pragma unroll
    for (int dn = 0; dn < 4; dn++) {
        *(float2*)(y + (size_t)(b * NN + r0) * CD + cB + dn * 8) =
            make_float2(acc[dn][0] * inv0, acc[dn][1] * inv0);
        *(float2*)(y + (size_t)(b * NN + r0 + 8) * CD + cB + dn * 8) =
            make_float2(acc[dn][2] * inv1, acc[dn][3] * inv1);
    }
}

// ---------------------------------------------------------------------------
// Fused LePE + split: yh/yl = split( y_attn + dwconv5x5(x) + bias )
// grid = (W, H, B), block = 128 threads (4 channels each)
// ---------------------------------------------------------------------------
__global__ __launch_bounds__(128) void lepe_split_kernel(
    const float* __restrict__ x, const float* __restrict__ wl,
    const float* __restrict__ bl, const float* __restrict__ y,
    __nv_bfloat16* __restrict__ yh, __nv_bfloat16* __restrict__ yl)
{
    const int b  = blockIdx.z;
    const int yy = blockIdx.y;
    const int xx = blockIdx.x;
    const int c  = threadIdx.x * 4;

    float4 sum = *(const float4*)&bl[c];
    #pragma unroll
    for (int ky = 0; ky < 5; ky++) {
        const int iy = yy + ky - 2;
        if (iy < 0 || iy >= HH) continue;
        #pragma unroll
        for (int kx = 0; kx < 5; kx++) {
            const int ix = xx + kx - 2;
            if (ix < 0 || ix >= WWI) continue;
            const float4 xv = *(const float4*)&x[(((size_t)(b * HH + iy) * WWI + ix) * CD) + c];
            const int wk = ky * 5 + kx;
            sum.x = fmaf(xv.x, wl[(c + 0) * 25 + wk], sum.x);
            sum.y = fmaf(xv.y, wl[(c + 1) * 25 + wk], sum.y);
            sum.z = fmaf(xv.z, wl[(c + 2) * 25 + wk], sum.z);
            sum.w = fmaf(xv.w, wl[(c + 3) * 25 + wk], sum.w);
        }
    }
    const size_t idx = (((size_t)b * NN + yy * WWI + xx) * CD) + c;
    const float4 av = *(const float4*)&y[idx];
    sum.x += av.x; sum.y += av.y; sum.z += av.z; sum.w += av.w;
    uint32_t h0, l0, h1, l1;
    split_pack(sum.x, sum.y, h0, l0);
    split_pack(sum.z, sum.w, h1, l1);
    uint32_t* H = (uint32_t*)(yh + idx);
    uint32_t* L = (uint32_t*)(yl + idx);
    H[0] = h0; H[1] = h1;
    L[0] = l0; L[1] = l1;
}

// ---------------------------------------------------------------------------
extern "C" void kernel_launch(void* const* d_in, const int* in_sizes, int n_in,
                              void* d_out, int out_size)
{
    const float* x      = (const float*)d_in[0];
    const float* w_qkv  = (const float*)d_in[1];
    const float* w_proj = (const float*)d_in[2];
    const float* b_proj = (const float*)d_in[3];
    const float* w_lepe = (const float*)d_in[4];
    const float* b_lepe = (const float*)d_in[5];
    float* out = (float*)d_out;

    float *yPtr;
    __nv_bfloat16 *xh, *xl, *yh, *yl, *wqh, *wql, *wph, *wpl;
    cudaGetSymbolAddress((void**)&yPtr, g_y);
    cudaGetSymbolAddress((void**)&xh, g_xh);   cudaGetSymbolAddress((void**)&xl, g_xl);
    cudaGetSymbolAddress((void**)&yh, g_yh);   cudaGetSymbolAddress((void**)&yl, g_yl);
    cudaGetSymbolAddress((void**)&wqh, g_wqh); cudaGetSymbolAddress((void**)&wql, g_wql);
    cudaGetSymbolAddress((void**)&wph, g_wph); cudaGetSymbolAddress((void**)&wpl, g_wpl);

    constexpr int SMEM_GEMM = 2 * 4 * 128 * 64;              // 65536 B
    constexpr int SMEM_ATTN = 2 * 128 * 64 + 2 * 4 * 64 * 64;  // 16384 + 32768 = 49152 B
    cudaFuncSetAttribute(mma_gemm<0>, cudaFuncAttributeMaxDynamicSharedMemorySize, SMEM_GEMM);
    cudaFuncSetAttribute(mma_gemm<1>, cudaFuncAttributeMaxDynamicSharedMemorySize, SMEM_GEMM);
    cudaFuncSetAttribute(attn_mma_kernel, cudaFuncAttributeMaxDynamicSharedMemorySize, SMEM_ATTN);

    // 0) split inputs/weights to bf16 hi/lo
    {
        int n4 = MTOT * CD / 4;
        split_kernel<<<(n4 + 255) / 256, 256>>>(x, xh, xl, n4);
        int w4 = 3 * CD * CD / 4;
        split_kernel<<<(w4 + 255) / 256, 256>>>(w_qkv, wqh, wql, w4);
        int p4 = CD * CD / 4;
        split_kernel<<<(p4 + 255) / 256, 256>>>(w_proj, wph, wpl, p4);
    }
    // 1) QKV projection -> g_{q,k,v}{h,l}   (M=8192, N=1536, K=512)
    {
        dim3 grid(3 * CD / 128, MTOT / 128);
        mma_gemm<0><<<grid, 256, SMEM_GEMM>>>(xh, xl, wqh, wql, nullptr, nullptr);
    }
    // 2) Attention -> g_y (fp32)
    {
        dim3 grid(NN / 128, NHEAD, BB);
        attn_mma_kernel<<<grid, 256, SMEM_ATTN>>>(yPtr);
    }
    // 3) Fused LePE + split -> g_yh/g_yl
    {
        dim3 grid(WWI, HH, BB);
        lepe_split_kernel<<<grid, 128>>>(x, w_lepe, b_lepe, yPtr, yh, yl);
    }
    // 4) Output projection -> d_out  (M=8192, N=512, K=512)
    {
        dim3 grid(CD / 128, MTOT / 128);
        mma_gemm<1><<<grid, 256, SMEM_GEMM>>>(yh, yl, wph, wpl, b_proj, out);
    }
}